// round 1
// baseline (speedup 1.0000x reference)
#include <cuda_runtime.h>
#include <cuda_bf16.h>
#include <math.h>

#define NN 50000
#define EE 800000
#define INC 128
#define HC 128
#define HID 32
#define HEADS 4
#define OUTC 64
#define ED 32
#define NEG 0.2f

// ---------------- scratch (device globals; no allocation allowed) -------------
__device__ float g_xl1[NN * HC];
__device__ float g_xr1[NN * HC];
__device__ float g_h  [NN * HC];
__device__ float g_xl2[NN * OUTC];
__device__ float g_xr2[NN * OUTC];
__device__ float g_a1 [EE * HEADS];
__device__ float g_a2 [EE];
__device__ int   g_deg[NN];
__device__ int   g_rowptr[NN + 1];
__device__ int   g_cursor[NN];
__device__ int   g_perm[EE];

__device__ __forceinline__ float lrelu(float x) { return x > 0.f ? x : NEG * x; }

// ---------------- CSR build ---------------------------------------------------
__global__ void zero_deg_kernel() {
    int i = blockIdx.x * blockDim.x + threadIdx.x;
    if (i < NN) g_deg[i] = 0;
}

__global__ void csr_count_kernel(const int* __restrict__ dst) {
    int e = blockIdx.x * blockDim.x + threadIdx.x;
    if (e < EE) atomicAdd(&g_deg[dst[e]], 1);
}

__global__ void scan_kernel() {
    __shared__ int sh[1024];
    int tid = threadIdx.x;
    int base_sum = 0;
    for (int base = 0; base < NN; base += 1024) {
        int idx = base + tid;
        int v = (idx < NN) ? g_deg[idx] : 0;
        sh[tid] = v;
        __syncthreads();
        for (int off = 1; off < 1024; off <<= 1) {
            int tv = (tid >= off) ? sh[tid - off] : 0;
            __syncthreads();
            sh[tid] += tv;
            __syncthreads();
        }
        int excl = sh[tid] - v;
        if (idx < NN) { g_rowptr[idx] = base_sum + excl; g_cursor[idx] = base_sum + excl; }
        int chunk_total = sh[1023];
        __syncthreads();
        base_sum += chunk_total;
    }
    if (tid == 0) g_rowptr[NN] = base_sum;
}

__global__ void csr_fill_kernel(const int* __restrict__ dst) {
    int e = blockIdx.x * blockDim.x + threadIdx.x;
    if (e < EE) {
        int pos = atomicAdd(&g_cursor[dst[e]], 1);
        g_perm[pos] = e;
    }
}

// ---------------- node linear transforms (xl = x@Wl+bl, xr = x@Wr+br) ---------
template<int INDIM, int OUTDIM>
__global__ void transform_kernel(const float* __restrict__ x,
                                 const float* __restrict__ Wl, const float* __restrict__ bl,
                                 const float* __restrict__ Wr, const float* __restrict__ br,
                                 float* __restrict__ xl, float* __restrict__ xr) {
    __shared__ float xs[4][INDIM];
    int node0 = blockIdx.x * 4;
    int t = threadIdx.x;   // 0..OUTDIM-1
    for (int idx = t; idx < 4 * INDIM; idx += OUTDIM) {
        int nn = idx / INDIM, k = idx % INDIM;
        int node = node0 + nn;
        xs[nn][k] = (node < NN) ? x[node * INDIM + k] : 0.f;
    }
    __syncthreads();
    float accl[4] = {0.f, 0.f, 0.f, 0.f};
    float accr[4] = {0.f, 0.f, 0.f, 0.f};
    #pragma unroll 4
    for (int k = 0; k < INDIM; k++) {
        float wl = Wl[k * OUTDIM + t];
        float wr = Wr[k * OUTDIM + t];
        #pragma unroll
        for (int nn = 0; nn < 4; nn++) {
            float xv = xs[nn][k];
            accl[nn] = fmaf(xv, wl, accl[nn]);
            accr[nn] = fmaf(xv, wr, accr[nn]);
        }
    }
    float blv = bl[t], brv = br[t];
    #pragma unroll
    for (int nn = 0; nn < 4; nn++) {
        int node = node0 + nn;
        if (node < NN) {
            xl[node * OUTDIM + t] = accl[nn] + blv;
            xr[node * OUTDIM + t] = accr[nn] + brv;
        }
    }
}

// ---------------- layer-1 edge logits -----------------------------------------
// a1[e,h] = att1[h,:] . lrelu(xl1[src] + xr1[dst] + ea@We1)
// one warp handles 4 edges; lane L owns channels 4L..4L+3 (head = L/8)
__global__ void edge_logits1_kernel(const int* __restrict__ src, const int* __restrict__ dst,
                                    const float* __restrict__ ea,
                                    const float* __restrict__ We, const float* __restrict__ att) {
    __shared__ float we_sm[ED * HC];     // 16 KB
    __shared__ float att_sm[HC];
    int t = threadIdx.x;
    for (int i = t; i < ED * HC; i += blockDim.x) we_sm[i] = We[i];
    if (t < HC) att_sm[t] = att[t];      // att1 is [4,32] contiguous == flat channel index
    __syncthreads();

    int warp = (blockIdx.x * blockDim.x + t) >> 5;
    int lane = t & 31;
    int ngroups = EE / 4;
    if (warp >= ngroups) return;
    int ebase = warp * 4;

    float eav[4];
    #pragma unroll
    for (int j = 0; j < 4; j++) eav[j] = ea[(ebase + j) * ED + lane];

    float4 acc[4];
    #pragma unroll
    for (int j = 0; j < 4; j++) acc[j] = make_float4(0.f, 0.f, 0.f, 0.f);

    int c0 = 4 * lane;
    #pragma unroll
    for (int k = 0; k < ED; k++) {
        float4 w = *(const float4*)&we_sm[k * HC + c0];
        #pragma unroll
        for (int j = 0; j < 4; j++) {
            float b = __shfl_sync(0xffffffffu, eav[j], k);
            acc[j].x = fmaf(b, w.x, acc[j].x);
            acc[j].y = fmaf(b, w.y, acc[j].y);
            acc[j].z = fmaf(b, w.z, acc[j].z);
            acc[j].w = fmaf(b, w.w, acc[j].w);
        }
    }

    float4 av = *(const float4*)&att_sm[c0];
    #pragma unroll
    for (int j = 0; j < 4; j++) {
        int e = ebase + j;
        int s = src[e], d = dst[e];
        float4 xlv = *(const float4*)&g_xl1[s * HC + c0];
        float4 xrv = *(const float4*)&g_xr1[d * HC + c0];
        float s0 = acc[j].x + xlv.x + xrv.x;
        float s1 = acc[j].y + xlv.y + xrv.y;
        float s2 = acc[j].z + xlv.z + xrv.z;
        float s3 = acc[j].w + xlv.w + xrv.w;
        float p = lrelu(s0) * av.x + lrelu(s1) * av.y + lrelu(s2) * av.z + lrelu(s3) * av.w;
        p += __shfl_xor_sync(0xffffffffu, p, 1);
        p += __shfl_xor_sync(0xffffffffu, p, 2);
        p += __shfl_xor_sync(0xffffffffu, p, 4);
        if ((lane & 7) == 0) g_a1[e * HEADS + (lane >> 3)] = p;
    }
}

// ---------------- layer-1 softmax + aggregate + bias + elu --------------------
// one warp per dst node; lane L owns channels 4L..4L+3 (head = L/8)
__global__ void aggregate1_kernel(const int* __restrict__ src, const float* __restrict__ bias) {
    int i = (blockIdx.x * blockDim.x + threadIdx.x) >> 5;
    int lane = threadIdx.x & 31;
    if (i >= NN) return;
    int start = g_rowptr[i], end = g_rowptr[i + 1];

    // per-head max: lane handles head lane&3, edges strided by 8
    int hmax = lane & 3;
    float m = -INFINITY;
    for (int j = start + (lane >> 2); j < end; j += 8) {
        int e = g_perm[j];
        m = fmaxf(m, g_a1[e * HEADS + hmax]);
    }
    m = fmaxf(m, __shfl_xor_sync(0xffffffffu, m, 4));
    m = fmaxf(m, __shfl_xor_sync(0xffffffffu, m, 8));
    m = fmaxf(m, __shfl_xor_sync(0xffffffffu, m, 16));
    int myh = lane >> 3;                                  // head this lane aggregates
    float mh = __shfl_sync(0xffffffffu, m, myh);          // lane h holds m_h

    float den = 0.f;
    float a0 = 0.f, a1 = 0.f, a2 = 0.f, a3 = 0.f;
    int c0 = 4 * lane;
    for (int j = start; j < end; j++) {
        int e = g_perm[j];
        float w = __expf(g_a1[e * HEADS + myh] - mh);
        int s = src[e];
        float4 xlv = *(const float4*)&g_xl1[s * HC + c0];
        den += w;
        a0 = fmaf(w, xlv.x, a0);
        a1 = fmaf(w, xlv.y, a1);
        a2 = fmaf(w, xlv.z, a2);
        a3 = fmaf(w, xlv.w, a3);
    }
    float inv = 1.f / (den + 1e-16f);
    float4 bv = *(const float4*)&bias[c0];
    float o0 = a0 * inv + bv.x;
    float o1 = a1 * inv + bv.y;
    float o2 = a2 * inv + bv.z;
    float o3 = a3 * inv + bv.w;
    // elu
    o0 = o0 > 0.f ? o0 : expm1f(o0);
    o1 = o1 > 0.f ? o1 : expm1f(o1);
    o2 = o2 > 0.f ? o2 : expm1f(o2);
    o3 = o3 > 0.f ? o3 : expm1f(o3);
    *(float4*)&g_h[i * HC + c0] = make_float4(o0, o1, o2, o3);
}

// ---------------- layer-2 edge logits -----------------------------------------
// a2[e] = att2 . lrelu(xl2[src] + xr2[dst] + ea@We2); single head, 64 channels
__global__ void edge_logits2_kernel(const int* __restrict__ src, const int* __restrict__ dst,
                                    const float* __restrict__ ea,
                                    const float* __restrict__ We, const float* __restrict__ att) {
    __shared__ float we_sm[ED * OUTC];   // 8 KB
    __shared__ float att_sm[OUTC];
    int t = threadIdx.x;
    for (int i = t; i < ED * OUTC; i += blockDim.x) we_sm[i] = We[i];
    if (t < OUTC) att_sm[t] = att[t];
    __syncthreads();

    int warp = (blockIdx.x * blockDim.x + t) >> 5;
    int lane = t & 31;
    int ngroups = EE / 4;
    if (warp >= ngroups) return;
    int ebase = warp * 4;

    float eav[4];
    #pragma unroll
    for (int j = 0; j < 4; j++) eav[j] = ea[(ebase + j) * ED + lane];

    float2 acc[4];
    #pragma unroll
    for (int j = 0; j < 4; j++) acc[j] = make_float2(0.f, 0.f);

    int c0 = 2 * lane;
    #pragma unroll
    for (int k = 0; k < ED; k++) {
        float2 w = *(const float2*)&we_sm[k * OUTC + c0];
        #pragma unroll
        for (int j = 0; j < 4; j++) {
            float b = __shfl_sync(0xffffffffu, eav[j], k);
            acc[j].x = fmaf(b, w.x, acc[j].x);
            acc[j].y = fmaf(b, w.y, acc[j].y);
        }
    }

    float2 av = *(const float2*)&att_sm[c0];
    #pragma unroll
    for (int j = 0; j < 4; j++) {
        int e = ebase + j;
        int s = src[e], d = dst[e];
        float2 xlv = *(const float2*)&g_xl2[s * OUTC + c0];
        float2 xrv = *(const float2*)&g_xr2[d * OUTC + c0];
        float s0 = acc[j].x + xlv.x + xrv.x;
        float s1 = acc[j].y + xlv.y + xrv.y;
        float p = lrelu(s0) * av.x + lrelu(s1) * av.y;
        p += __shfl_xor_sync(0xffffffffu, p, 1);
        p += __shfl_xor_sync(0xffffffffu, p, 2);
        p += __shfl_xor_sync(0xffffffffu, p, 4);
        p += __shfl_xor_sync(0xffffffffu, p, 8);
        p += __shfl_xor_sync(0xffffffffu, p, 16);
        if (lane == 0) g_a2[e] = p;
    }
}

// ---------------- layer-2 softmax + aggregate + bias --------------------------
__global__ void aggregate2_kernel(const int* __restrict__ src, const float* __restrict__ bias,
                                  float* __restrict__ out) {
    int i = (blockIdx.x * blockDim.x + threadIdx.x) >> 5;
    int lane = threadIdx.x & 31;
    if (i >= NN) return;
    int start = g_rowptr[i], end = g_rowptr[i + 1];

    float m = -INFINITY;
    for (int j = start + lane; j < end; j += 32) {
        m = fmaxf(m, g_a2[g_perm[j]]);
    }
    m = fmaxf(m, __shfl_xor_sync(0xffffffffu, m, 1));
    m = fmaxf(m, __shfl_xor_sync(0xffffffffu, m, 2));
    m = fmaxf(m, __shfl_xor_sync(0xffffffffu, m, 4));
    m = fmaxf(m, __shfl_xor_sync(0xffffffffu, m, 8));
    m = fmaxf(m, __shfl_xor_sync(0xffffffffu, m, 16));

    float den = 0.f;
    float a0 = 0.f, a1 = 0.f;
    int c0 = 2 * lane;
    for (int j = start; j < end; j++) {
        int e = g_perm[j];
        float w = __expf(g_a2[e] - m);
        int s = src[e];
        float2 xlv = *(const float2*)&g_xl2[s * OUTC + c0];
        den += w;
        a0 = fmaf(w, xlv.x, a0);
        a1 = fmaf(w, xlv.y, a1);
    }
    float inv = 1.f / (den + 1e-16f);
    float o0 = a0 * inv + bias[c0];
    float o1 = a1 * inv + bias[c0 + 1];
    *(float2*)&out[i * OUTC + c0] = make_float2(o0, o1);
}

// ---------------- host launcher ------------------------------------------------
extern "C" void kernel_launch(void* const* d_in, const int* in_sizes, int n_in,
                              void* d_out, int out_size) {
    const float* x    = (const float*)d_in[0];
    const int*   ei   = (const int*)  d_in[1];
    const float* ea   = (const float*)d_in[2];
    const float* Wl1  = (const float*)d_in[3];
    const float* bl1  = (const float*)d_in[4];
    const float* Wr1  = (const float*)d_in[5];
    const float* br1  = (const float*)d_in[6];
    const float* We1  = (const float*)d_in[7];
    const float* att1 = (const float*)d_in[8];
    const float* bias1= (const float*)d_in[9];
    const float* Wl2  = (const float*)d_in[10];
    const float* bl2  = (const float*)d_in[11];
    const float* Wr2  = (const float*)d_in[12];
    const float* br2  = (const float*)d_in[13];
    const float* We2  = (const float*)d_in[14];
    const float* att2 = (const float*)d_in[15];
    const float* bias2= (const float*)d_in[16];

    const int* src = ei;
    const int* dst = ei + EE;

    void *p_xl1, *p_xr1, *p_h, *p_xl2, *p_xr2;
    cudaGetSymbolAddress(&p_xl1, g_xl1);
    cudaGetSymbolAddress(&p_xr1, g_xr1);
    cudaGetSymbolAddress(&p_h,   g_h);
    cudaGetSymbolAddress(&p_xl2, g_xl2);
    cudaGetSymbolAddress(&p_xr2, g_xr2);

    // CSR by dst
    zero_deg_kernel<<<(NN + 255) / 256, 256>>>();
    csr_count_kernel<<<EE / 256, 256>>>(dst);
    scan_kernel<<<1, 1024>>>();
    csr_fill_kernel<<<EE / 256, 256>>>(dst);

    // layer 1
    transform_kernel<INC, HC><<<NN / 4, HC>>>(x, Wl1, bl1, Wr1, br1, (float*)p_xl1, (float*)p_xr1);
    edge_logits1_kernel<<<(EE / 4) / 8, 256>>>(src, dst, ea, We1, att1);
    aggregate1_kernel<<<NN / 8, 256>>>(src, bias1);

    // layer 2
    transform_kernel<HC, OUTC><<<NN / 4, OUTC>>>((const float*)p_h, Wl2, bl2, Wr2, br2,
                                                 (float*)p_xl2, (float*)p_xr2);
    edge_logits2_kernel<<<(EE / 4) / 8, 256>>>(src, dst, ea, We2, att2);
    aggregate2_kernel<<<NN / 8, 256>>>(src, bias2, (float*)d_out);
}